// round 1
// baseline (speedup 1.0000x reference)
#include <cuda_runtime.h>
#include <math.h>

// ---------------------------------------------------------------------------
// RDAB block: x[16,64,128,128] fp32
//   out = conv2(leaky(rda2(leaky(conv1(leaky(rda1(x,d)))),d))) + x
// Heavy cost: two dense 64->64 3x3 convs (9.66 GMAC each, fp32).
// ---------------------------------------------------------------------------

#define B_   16
#define C_   64
#define H_   128
#define W_   128
#define HW_  (H_*W_)
#define CHW_ (C_*HW_)

// scratch (device globals: allocation-free per harness rules)
__device__ float g_buf1[(size_t)B_*CHW_];
__device__ float g_buf2[(size_t)B_*CHW_];
__device__ float g_gate[(size_t)B_*HW_];
__device__ float g_kern1[B_*C_*9];
__device__ float g_kern2[B_*C_*9];

__device__ __forceinline__ float leaky01(float v) {
    return v > 0.f ? v : 0.1f * v;
}

// ---------------------------------------------------------------------------
// 1) dynamic-kernel MLP:  hid = leaky(d @ k1);  kern = hid @ k2
//    grid = (16 batches, 2 stages), 64 threads
// ---------------------------------------------------------------------------
__global__ void mlp_kernel(const float* __restrict__ d,
                           const float* __restrict__ k1a, const float* __restrict__ k2a,
                           const float* __restrict__ k1b, const float* __restrict__ k2b,
                           float* __restrict__ kern1, float* __restrict__ kern2)
{
    int b = blockIdx.x;
    int stage = blockIdx.y;
    const float* k1 = stage ? k1b : k1a;
    const float* k2 = stage ? k2b : k2a;
    float* ko = stage ? kern2 : kern1;

    __shared__ float dd[64];
    __shared__ float hid[64];
    int t = threadIdx.x;
    dd[t] = d[b*64 + t];
    __syncthreads();
    float s = 0.f;
#pragma unroll 8
    for (int i = 0; i < 64; i++) s += dd[i] * k1[i*64 + t];
    hid[t] = leaky01(s);
    __syncthreads();
#pragma unroll
    for (int r = 0; r < 9; r++) {
        int o = r*64 + t;             // 0..575
        float s2 = 0.f;
#pragma unroll 8
        for (int i = 0; i < 64; i++) s2 += hid[i] * k2[i*576 + o];
        ko[b*576 + o] = s2;           // kern[b][c*9 + j], c = o/9
    }
}

// ---------------------------------------------------------------------------
// 2) gating map: M[b,h,w] = sigmoid( sum_c in[b,c,h,w]*cw[c] + cb )
// ---------------------------------------------------------------------------
__global__ void gate_kernel(const float* __restrict__ in,
                            const float* __restrict__ cw,
                            const float* __restrict__ cb,
                            float* __restrict__ M)
{
    __shared__ float scw[C_];
    if (threadIdx.x < C_) scw[threadIdx.x] = cw[threadIdx.x];
    __syncthreads();
    int idx = blockIdx.x * blockDim.x + threadIdx.x;   // over B_*HW_
    int b  = idx / HW_;
    int hw = idx - b * HW_;
    const float* p = in + (size_t)b * CHW_ + hw;
    float s = cb[0];
#pragma unroll 8
    for (int c = 0; c < C_; c++) s += scw[c] * p[(size_t)c * HW_];
    M[idx] = 1.f / (1.f + expf(-s));
}

// ---------------------------------------------------------------------------
// 3) fused RDA: out = leaky( leaky(dwconv3x3(in,kern)) * M + in )
//    (outer leaky belongs to the RDAB wrapper; both call sites apply it)
// ---------------------------------------------------------------------------
__global__ void rda_kernel(const float* __restrict__ in,
                           const float* __restrict__ kern,
                           const float* __restrict__ M,
                           float* __restrict__ out)
{
    int idx = blockIdx.x * blockDim.x + threadIdx.x;  // 0..HW_-1
    int c = blockIdx.y;
    int b = blockIdx.z;
    int h = idx >> 7;
    int w = idx & 127;

    const float* k = kern + (b*C_ + c) * 9;
    float k0 = k[0], k1 = k[1], k2 = k[2],
          k3 = k[3], k4 = k[4], k5 = k[5],
          k6 = k[6], k7 = k[7], k8 = k[8];

    const float* p = in + ((size_t)b*C_ + c) * HW_;
    float dw = 0.f;
    // row h-1
    if (h > 0) {
        const float* r = p + (h-1)*W_;
        if (w > 0)    dw += k0 * r[w-1];
                      dw += k1 * r[w];
        if (w < 127)  dw += k2 * r[w+1];
    }
    {
        const float* r = p + h*W_;
        if (w > 0)    dw += k3 * r[w-1];
                      dw += k4 * r[w];
        if (w < 127)  dw += k5 * r[w+1];
    }
    if (h < 127) {
        const float* r = p + (h+1)*W_;
        if (w > 0)    dw += k6 * r[w-1];
                      dw += k7 * r[w];
        if (w < 127)  dw += k8 * r[w+1];
    }
    float v = leaky01(dw);
    float m = M[(size_t)b*HW_ + idx];
    v = v * m + p[h*W_ + w];
    out[((size_t)b*C_ + c) * HW_ + idx] = leaky01(v);
}

// ---------------------------------------------------------------------------
// 4) dense 3x3 conv 64->64, smem-tiled.
//    Block: 128 threads, tile 32(w) x 16(h), 8 output channels per block,
//    each thread: 4 pixels x 8 co = 32 accumulators.
//    grid = (32 tiles, 8 co-groups, 16 batches)
// ---------------------------------------------------------------------------
#define TW 32
#define TH 16
#define COP 8

__global__ void __launch_bounds__(128, 8)
conv3x3_kernel(const float* __restrict__ in,
               const float* __restrict__ wgt,
               const float* __restrict__ bias,
               const float* __restrict__ residual,   // may be null
               float* __restrict__ out,
               int apply_leaky)
{
    __shared__ float sW[C_ * COP * 9];     // 18432 B, layout [ci][oc][k]
    __shared__ float sIn[18 * 36];         // 2592 B (34 cols padded to 36)

    int b    = blockIdx.z;
    int co0  = blockIdx.y * COP;
    int tile = blockIdx.x;
    int tx = tile & 3;            // 0..3  (W_/TW = 4)
    int ty = tile >> 2;           // 0..7  (H_/TH = 8)
    int w0 = tx * TW;
    int h0 = ty * TH;
    int tid = threadIdx.x;        // 0..127

    // stage all weights for this co-group once
    for (int i = tid; i < C_ * COP * 9; i += 128) {
        int ci  = i / (COP * 9);
        int rem = i - ci * (COP * 9);
        int oc  = rem / 9;
        int k   = rem - oc * 9;
        sW[i] = wgt[((co0 + oc) * C_ + ci) * 9 + k];
    }

    float acc[COP][4];
#pragma unroll
    for (int oc = 0; oc < COP; oc++)
#pragma unroll
        for (int p = 0; p < 4; p++) acc[oc][p] = 0.f;

    int row = tid >> 3;            // 0..15
    int wq  = (tid & 7) * 4;       // 0..28

    const float* inb = in + (size_t)b * CHW_;

    for (int ci = 0; ci < C_; ci++) {
        __syncthreads();           // protect sIn from previous iteration reads
        const float* cp = inb + (size_t)ci * HW_;
        for (int i = tid; i < 18 * 34; i += 128) {
            int ly = i / 34, lx = i - ly * 34;
            int gy = h0 - 1 + ly, gx = w0 - 1 + lx;
            float v = 0.f;
            if (gy >= 0 && gy < H_ && gx >= 0 && gx < W_) v = cp[gy * W_ + gx];
            sIn[ly * 36 + lx] = v;
        }
        __syncthreads();

        float r0[6], r1[6], r2[6];
#pragma unroll
        for (int c = 0; c < 6; c++) {
            r0[c] = sIn[(row    ) * 36 + wq + c];
            r1[c] = sIn[(row + 1) * 36 + wq + c];
            r2[c] = sIn[(row + 2) * 36 + wq + c];
        }
        const float* wc = &sW[ci * COP * 9];
#pragma unroll
        for (int oc = 0; oc < COP; oc++) {
            float q0 = wc[oc*9+0], q1 = wc[oc*9+1], q2 = wc[oc*9+2];
            float q3 = wc[oc*9+3], q4 = wc[oc*9+4], q5 = wc[oc*9+5];
            float q6 = wc[oc*9+6], q7 = wc[oc*9+7], q8 = wc[oc*9+8];
#pragma unroll
            for (int p = 0; p < 4; p++) {
                float a = acc[oc][p];
                a += q0 * r0[p]   + q1 * r0[p+1] + q2 * r0[p+2];
                a += q3 * r1[p]   + q4 * r1[p+1] + q5 * r1[p+2];
                a += q6 * r2[p]   + q7 * r2[p+1] + q8 * r2[p+2];
                acc[oc][p] = a;
            }
        }
    }

    // epilogue
#pragma unroll
    for (int oc = 0; oc < COP; oc++) {
        float bv = bias[co0 + oc];
        size_t base = (((size_t)b * C_ + co0 + oc) * H_ + (h0 + row)) * W_ + w0 + wq;
#pragma unroll
        for (int p = 0; p < 4; p++) {
            float v = acc[oc][p] + bv;
            if (apply_leaky) v = leaky01(v);
            if (residual) v += residual[base + p];
            out[base + p] = v;
        }
    }
}

// ---------------------------------------------------------------------------
// launch
// ---------------------------------------------------------------------------
extern "C" void kernel_launch(void* const* d_in, const int* in_sizes, int n_in,
                              void* d_out, int out_size)
{
    const float* x       = (const float*)d_in[0];
    const float* d       = (const float*)d_in[1];
    const float* da1_k1  = (const float*)d_in[2];
    const float* da1_k2  = (const float*)d_in[3];
    const float* da1_cw  = (const float*)d_in[4];
    const float* da1_cb  = (const float*)d_in[5];
    const float* da2_k1  = (const float*)d_in[6];
    const float* da2_k2  = (const float*)d_in[7];
    const float* da2_cw  = (const float*)d_in[8];
    const float* da2_cb  = (const float*)d_in[9];
    const float* conv1_w = (const float*)d_in[10];
    const float* conv1_b = (const float*)d_in[11];
    const float* conv2_w = (const float*)d_in[12];
    const float* conv2_b = (const float*)d_in[13];
    float* out = (float*)d_out;

    float *buf1, *buf2, *gate, *kern1, *kern2;
    cudaGetSymbolAddress((void**)&buf1,  g_buf1);
    cudaGetSymbolAddress((void**)&buf2,  g_buf2);
    cudaGetSymbolAddress((void**)&gate,  g_gate);
    cudaGetSymbolAddress((void**)&kern1, g_kern1);
    cudaGetSymbolAddress((void**)&kern2, g_kern2);

    // 1) both dynamic-kernel MLPs
    mlp_kernel<<<dim3(B_, 2), 64>>>(d, da1_k1, da1_k2, da2_k1, da2_k2, kern1, kern2);

    // 2) gate1 from x
    gate_kernel<<<(B_*HW_)/256, 256>>>(x, da1_cw, da1_cb, gate);

    // 3) rda1: x -> buf1
    rda_kernel<<<dim3(HW_/256, C_, B_), 256>>>(x, kern1, gate, buf1);

    // 4) conv1 + leaky: buf1 -> buf2
    conv3x3_kernel<<<dim3(32, C_/COP, B_), 128>>>(buf1, conv1_w, conv1_b, nullptr, buf2, 1);

    // 5) gate2 from buf2
    gate_kernel<<<(B_*HW_)/256, 256>>>(buf2, da2_cw, da2_cb, gate);

    // 6) rda2: buf2 -> buf1
    rda_kernel<<<dim3(HW_/256, C_, B_), 256>>>(buf2, kern2, gate, buf1);

    // 7) conv2 + residual(x): buf1 -> out
    conv3x3_kernel<<<dim3(32, C_/COP, B_), 128>>>(buf1, conv2_w, conv2_b, x, out, 0);
}